// round 1
// baseline (speedup 1.0000x reference)
#include <cuda_runtime.h>
#include <cstdint>

// ---------------- problem constants ----------------
#define M_CANDS 131072
#define N_ROWS  2048
#define DIM     64
#define KSEL    11          // k+1 smallest, smallest (self) dropped

// ---------------- tiling ----------------
#define TM      16          // x rows per block
#define TN      256         // candidates per smem tile
#define THREADS 256
#define NT      (M_CANDS / TN)     // 512 tiles
#define BSTR    68          // padded floats per candidate row (conflict-free LDS.128)
#define DSTR    (TN + 16)   // 272, padded distance-tile stride

// ---------------- smem layout (floats) ----------------
#define BS_OFF  0
#define BS_BUF  (TN * BSTR)               // 17408 floats per buffer
#define XS_OFF  (2 * BS_BUF)              // 34816
#define DS_OFF  (XS_OFF + TM * DIM)       // 35840
#define BN_OFF  (DS_OFF + TM * DSTR)      // 40192
#define SMEM_FLOATS (BN_OFF + 2 * TN)     // 40704
#define SMEM_BYTES  (SMEM_FLOATS * 4)     // 162816 bytes

__device__ __align__(16) float g_bnorm[M_CANDS];

__device__ __forceinline__ uint32_t smem_u32(const void* p) {
    return (uint32_t)__cvta_generic_to_shared(p);
}
__device__ __forceinline__ void cp16(uint32_t dst, const void* gsrc) {
    asm volatile("cp.async.cg.shared.global [%0], [%1], 16;"
                 :: "r"(dst), "l"(__cvta_generic_to_global(gsrc)));
}

// |b|^2 for every cache row
__global__ void bnorm_kernel(const float* __restrict__ buf) {
    int c = blockIdx.x * blockDim.x + threadIdx.x;
    const float4* b4 = reinterpret_cast<const float4*>(buf) + (size_t)c * (DIM / 4);
    float s = 0.f;
#pragma unroll
    for (int q = 0; q < DIM / 4; ++q) {
        float4 v = b4[q];
        s = fmaf(v.x, v.x, s); s = fmaf(v.y, v.y, s);
        s = fmaf(v.z, v.z, s); s = fmaf(v.w, v.w, s);
    }
    g_bnorm[c] = s;
}

// keep h[0..10] = the 11 smallest seen, ascending; v known < h[10]
__device__ __forceinline__ void bubble_insert(float h[KSEL], float v) {
#pragma unroll
    for (int j = 0; j < KSEL; ++j) {
        float lo = fminf(h[j], v);
        v = fmaxf(h[j], v);
        h[j] = lo;
    }
}

extern __shared__ float smem[];

__global__ void __launch_bounds__(THREADS, 1)
pbe_main_kernel(const float* __restrict__ x, const float* __restrict__ buf,
                float* __restrict__ out) {
    const int tid = threadIdx.x;
    const int blk = blockIdx.x;

    // ---- load x tile (16 rows x 64) ----
    {
        int row = tid >> 4, q = tid & 15;
        float4 v = reinterpret_cast<const float4*>(x)[(size_t)(blk * TM + row) * (DIM / 4) + q];
        reinterpret_cast<float4*>(&smem[XS_OFF])[tid] = v;   // visible after first barrier
    }

    // ---- async staging of one candidate tile (+ its norms) ----
    auto stage = [&](int tile, int bsl) {
        const float4* bsrc = reinterpret_cast<const float4*>(buf)
                           + (size_t)tile * TN * (DIM / 4);
        uint32_t bs_base = smem_u32(&smem[BS_OFF + bsl * BS_BUF]);
#pragma unroll
        for (int r = 0; r < (TN * 16) / THREADS; ++r) {       // 16 x 16B per thread
            int idx = tid + r * THREADS;
            int c = idx >> 4, q = idx & 15;
            cp16(bs_base + (uint32_t)(c * BSTR + q * 4) * 4, bsrc + (size_t)c * 16 + q);
        }
        if (tid < TN / 4) {
            uint32_t d = smem_u32(&smem[BN_OFF + bsl * TN + tid * 4]);
            cp16(d, &g_bnorm[(size_t)tile * TN + tid * 4]);
        }
        asm volatile("cp.async.commit_group;");
    };

    stage(0, 0);

    const int cg   = tid & 63;   // candidate group (4 cands, interleaved by 64)
    const int rg   = tid >> 6;   // row group (4 rows)
    const int srow = tid >> 4;   // selection: owned row
    const int slot = tid & 15;   // selection: lane within row

    float h[KSEL];
#pragma unroll
    for (int j = 0; j < KSEL; ++j) h[j] = __int_as_float(0x7f800000);

    for (int t = 0; t < NT; ++t) {
        const int bsl = t & 1;
        if (t + 1 < NT) {
            stage(t + 1, bsl ^ 1);
            asm volatile("cp.async.wait_group 1;");
        } else {
            asm volatile("cp.async.wait_group 0;");
        }
        __syncthreads();   // tile t resident; xs resident (t==0)

        // ---- 4x4 register-tiled dot products over k ----
        float acc[4][4];
#pragma unroll
        for (int i = 0; i < 4; ++i)
#pragma unroll
            for (int j = 0; j < 4; ++j) acc[i][j] = 0.f;

        const float* bsb = &smem[BS_OFF + bsl * BS_BUF];
        const float* xsb = &smem[XS_OFF + rg * 4 * DIM];
#pragma unroll
        for (int k4 = 0; k4 < DIM / 4; ++k4) {
            float4 xa[4], bb[4];
#pragma unroll
            for (int i = 0; i < 4; ++i)
                xa[i] = *reinterpret_cast<const float4*>(&xsb[i * DIM + k4 * 4]);
#pragma unroll
            for (int j = 0; j < 4; ++j)
                bb[j] = *reinterpret_cast<const float4*>(&bsb[(cg + 64 * j) * BSTR + k4 * 4]);
#pragma unroll
            for (int i = 0; i < 4; ++i)
#pragma unroll
                for (int j = 0; j < 4; ++j) {
                    acc[i][j] = fmaf(xa[i].x, bb[j].x, acc[i][j]);
                    acc[i][j] = fmaf(xa[i].y, bb[j].y, acc[i][j]);
                    acc[i][j] = fmaf(xa[i].z, bb[j].z, acc[i][j]);
                    acc[i][j] = fmaf(xa[i].w, bb[j].w, acc[i][j]);
                }
        }
        // s = |b|^2 - 2*dot   (|x|^2 is row-constant; added in the epilogue)
#pragma unroll
        for (int j = 0; j < 4; ++j) {
            float bn = smem[BN_OFF + bsl * TN + cg + 64 * j];
#pragma unroll
            for (int i = 0; i < 4; ++i)
                smem[DS_OFF + (rg * 4 + i) * DSTR + cg + 64 * j] = fmaf(-2.f, acc[i][j], bn);
        }
        __syncthreads();   // distance tile complete

        // ---- per-row selection: 16 threads/row, sorted-11 registers ----
#pragma unroll
        for (int i = 0; i < TN / 16; ++i) {
            float s = smem[DS_OFF + srow * DSTR + slot + 16 * i];
            if (s < h[KSEL - 1]) bubble_insert(h, s);
        }
        __syncthreads();   // everyone done with ds & bs[bsl]
    }

    // ---- merge the 16 sorted lists per row ----
#pragma unroll
    for (int j = 0; j < KSEL; ++j)
        smem[DS_OFF + (srow * 16 + slot) * KSEL + j] = h[j];
    __syncthreads();

    if (tid < TM) {
        const int row = tid;
        float best[KSEL];
#pragma unroll
        for (int j = 0; j < KSEL; ++j) best[j] = __int_as_float(0x7f800000);
        for (int tt = 0; tt < 16; ++tt) {
            for (int j = 0; j < KSEL; ++j) {
                float v = smem[DS_OFF + (row * 16 + tt) * KSEL + j];
                if (v < best[KSEL - 1]) bubble_insert(best, v);
                else break;              // each list is sorted ascending
            }
        }
        float xn = 0.f;
        for (int k = 0; k < DIM; ++k) {
            float xv = smem[XS_OFF + row * DIM + k];
            xn = fmaf(xv, xv, xn);
        }
        float s = 0.f;
#pragma unroll
        for (int j = 1; j < KSEL; ++j)          // drop self-match (best[0])
            s += sqrtf(fmaxf(xn + best[j], 0.f));
        out[blk * TM + row] = log1pf(s * (1.f / (KSEL - 1)));
    }
}

extern "C" void kernel_launch(void* const* d_in, const int* in_sizes, int n_in,
                              void* d_out, int out_size) {
    const float* a = (const float*)d_in[0];
    const float* b = (const float*)d_in[1];
    // x has 2048*64 = 131072 elems, buf has 131072*64; disambiguate by size
    const float* x   = a;
    const float* buf = b;
    if (in_sizes[0] > in_sizes[1]) { x = b; buf = a; }

    cudaFuncSetAttribute(pbe_main_kernel,
                         cudaFuncAttributeMaxDynamicSharedMemorySize, SMEM_BYTES);

    bnorm_kernel<<<M_CANDS / 256, 256>>>(buf);
    pbe_main_kernel<<<N_ROWS / TM, THREADS, SMEM_BYTES>>>(x, buf, (float*)d_out);
}

// round 3
// speedup vs baseline: 3.3146x; 3.3146x over previous
#include <cuda_runtime.h>
#include <cuda_bf16.h>
#include <cstdint>

// ---------------- problem constants ----------------
#define M_CANDS 131072
#define N_ROWS  2048
#define DIM     64
#define KSEL    11                 // k+1 smallest; smallest (self) dropped later

// ---------------- tiling ----------------
#define PARTS    16                      // candidate partitions
#define ROWS_CTA 256                     // x rows per CTA (8 warps x 32 rows)
#define ROWTILES (N_ROWS / ROWS_CTA)     // 8
#define CPART    (M_CANDS / PARTS)       // 8192 candidates per CTA
#define TN       256                     // candidates per smem tile
#define NT       (CPART / TN)            // 32 tiles
#define THREADS  256

// ---------------- smem layout (bytes) ----------------
#define B_SLOT   (TN * 128)              // 32768 (bf16, 128B/cand, SW128)
#define SM_B     0
#define SM_BN    (3 * B_SLOT)            // 98304
#define BN_SLOT  (TN * 4)                // 1024
#define SMEM_TOTAL (SM_BN + 3 * BN_SLOT) // 101376

// ---------------- device globals (allocation-free scratch) ----------------
__device__ __align__(16) __nv_bfloat16 g_bbf[(size_t)M_CANDS * DIM];   // -2*buf in bf16
__device__ __align__(16) __nv_bfloat16 g_xbf[(size_t)N_ROWS * DIM];
__device__ __align__(16) float g_bnorm[M_CANDS];
__device__ __align__(16) float g_partial[(size_t)N_ROWS * PARTS * 4 * KSEL];

// ---------------- helpers ----------------
__device__ __forceinline__ uint32_t smem_u32(const void* p) {
    return (uint32_t)__cvta_generic_to_shared(p);
}
__device__ __forceinline__ void cp16(uint32_t dst, const void* gsrc) {
    asm volatile("cp.async.cg.shared.global [%0], [%1], 16;"
                 :: "r"(dst), "l"(__cvta_generic_to_global(gsrc)));
}
#define CP_COMMIT() asm volatile("cp.async.commit_group;")
#define CP_WAIT1()  asm volatile("cp.async.wait_group 1;")
#define SWZ128(off) ((off) ^ (((off) >> 3) & 0x70))

// m16n8k16 row.col bf16 -> f32, D += A*B (D aliases C)
__device__ __forceinline__ void mma16816(float c[4], const uint32_t a[4],
                                         uint32_t b0, uint32_t b1) {
    asm volatile(
        "mma.sync.aligned.m16n8k16.row.col.f32.bf16.bf16.f32 "
        "{%0,%1,%2,%3}, {%4,%5,%6,%7}, {%8,%9}, {%0,%1,%2,%3};"
        : "+f"(c[0]), "+f"(c[1]), "+f"(c[2]), "+f"(c[3])
        : "r"(a[0]), "r"(a[1]), "r"(a[2]), "r"(a[3]), "r"(b0), "r"(b1));
}

// keep h[0..10] ascending; caller ensured v < h[10]
__device__ __forceinline__ void bubble_insert(float* h, float v) {
#pragma unroll
    for (int j = 0; j < KSEL; ++j) {
        float lo = fminf(h[j], v);
        v = fmaxf(h[j], v);
        h[j] = lo;
    }
}

// ---------------- prep kernels ----------------
__global__ void prep_buf_kernel(const float* __restrict__ buf) {
    int c = blockIdx.x * 256 + threadIdx.x;
    const float4* s = reinterpret_cast<const float4*>(buf) + (size_t)c * 16;
    uint4 pk[8];
    uint32_t* pw = reinterpret_cast<uint32_t*>(pk);
    float n = 0.f;
#pragma unroll
    for (int q = 0; q < 16; ++q) {
        float4 v = s[q];
        n = fmaf(v.x, v.x, n); n = fmaf(v.y, v.y, n);
        n = fmaf(v.z, v.z, n); n = fmaf(v.w, v.w, n);
        __nv_bfloat162 a = __floats2bfloat162_rn(-2.f * v.x, -2.f * v.y);
        __nv_bfloat162 b = __floats2bfloat162_rn(-2.f * v.z, -2.f * v.w);
        pw[2 * q]     = reinterpret_cast<uint32_t&>(a);
        pw[2 * q + 1] = reinterpret_cast<uint32_t&>(b);
    }
    uint4* dst = reinterpret_cast<uint4*>(g_bbf) + (size_t)c * 8;
#pragma unroll
    for (int i = 0; i < 8; ++i) dst[i] = pk[i];
    g_bnorm[c] = n;
}

__global__ void prep_x_kernel(const float* __restrict__ x) {
    int c = blockIdx.x * 256 + threadIdx.x;
    const float4* s = reinterpret_cast<const float4*>(x) + (size_t)c * 16;
    uint4 pk[8];
    uint32_t* pw = reinterpret_cast<uint32_t*>(pk);
#pragma unroll
    for (int q = 0; q < 16; ++q) {
        float4 v = s[q];
        __nv_bfloat162 a = __floats2bfloat162_rn(v.x, v.y);
        __nv_bfloat162 b = __floats2bfloat162_rn(v.z, v.w);
        pw[2 * q]     = reinterpret_cast<uint32_t&>(a);
        pw[2 * q + 1] = reinterpret_cast<uint32_t&>(b);
    }
    uint4* dst = reinterpret_cast<uint4*>(g_xbf) + (size_t)c * 8;
#pragma unroll
    for (int i = 0; i < 8; ++i) dst[i] = pk[i];
}

// ---------------- main fused GEMM + top-k kernel ----------------
extern __shared__ char smem[];

__global__ void __launch_bounds__(THREADS, 1)
pbe_mma_kernel() {
    const int tid  = threadIdx.x;
    const int lane = tid & 31;
    const int w    = tid >> 5;
    const int g    = lane >> 2;          // group id (0..7)
    const int tig  = lane & 3;           // thread in group
    const int part = blockIdx.x;
    const int rt   = blockIdx.y;
    const int cand_base = part * CPART;
    const int row_base  = rt * ROWS_CTA + w * 32;

    const uint32_t sbase = smem_u32(smem);

    // ---- A fragments (persistent, loaded once from global bf16 x) ----
    // afr[mb][kc][0..3]: rows (row_base+mb*16+g, +8), k = kc*16 + tig*2 (+8)
    uint32_t afr[2][4][4];
#pragma unroll
    for (int mb = 0; mb < 2; ++mb) {
        const uint32_t* x0 = reinterpret_cast<const uint32_t*>(
            g_xbf + (size_t)(row_base + mb * 16 + g) * DIM);
        const uint32_t* x1 = reinterpret_cast<const uint32_t*>(
            g_xbf + (size_t)(row_base + mb * 16 + g + 8) * DIM);
#pragma unroll
        for (int kc = 0; kc < 4; ++kc) {
            afr[mb][kc][0] = x0[kc * 8 + tig];
            afr[mb][kc][1] = x1[kc * 8 + tig];
            afr[mb][kc][2] = x0[kc * 8 + tig + 4];
            afr[mb][kc][3] = x1[kc * 8 + tig + 4];
        }
    }

    // ---- staging: B tile (SW128 swizzled) + its norms, triple-buffered ----
    auto stage = [&](int t, int slot) {
        const char* src = reinterpret_cast<const char*>(g_bbf)
                        + ((size_t)(cand_base + t * TN)) * (DIM * 2);
        uint32_t bb = sbase + SM_B + slot * B_SLOT;
#pragma unroll
        for (int r = 0; r < 8; ++r) {                    // 2048 x 16B total
            int idx = tid + r * THREADS;
            int c = idx >> 3, q = idx & 7;
            cp16(bb + SWZ128((uint32_t)(c * 128 + q * 16)), src + c * 128 + q * 16);
        }
        if (tid < TN / 4)
            cp16(sbase + SM_BN + slot * BN_SLOT + tid * 16,
                 g_bnorm + cand_base + t * TN + tid * 4);
    };

    stage(0, 0); CP_COMMIT();
    stage(1, 1); CP_COMMIT();

    // ---- top-11 lists for this thread's 4 rows ----
    float h[4][KSEL];
#pragma unroll
    for (int r = 0; r < 4; ++r)
#pragma unroll
        for (int j = 0; j < KSEL; ++j) h[r][j] = __int_as_float(0x7f800000);

    for (int t = 0; t < NT; ++t) {
        const int slot = t % 3;
        CP_WAIT1();
        __syncthreads();                 // tile t resident; slot (t+2)%3 free

        // prefetch tile t+2 (overlaps the compute below)
        if (t + 2 < NT) stage(t + 2, (t + 2) % 3);
        CP_COMMIT();

        const char*  bsm = smem + SM_B + slot * B_SLOT;
        const float* bns = reinterpret_cast<const float*>(smem + SM_BN + slot * BN_SLOT);

#pragma unroll
        for (int ncb = 0; ncb < 8; ++ncb) {              // 8 chunks x 32 cands
            float acc[4][2][4];
#pragma unroll
            for (int nb = 0; nb < 4; ++nb) {
                const float2 bnv = *reinterpret_cast<const float2*>(
                    &bns[(ncb * 4 + nb) * 8 + tig * 2]);
#pragma unroll
                for (int mb = 0; mb < 2; ++mb) {
                    acc[nb][mb][0] = bnv.x; acc[nb][mb][1] = bnv.y;
                    acc[nb][mb][2] = bnv.x; acc[nb][mb][3] = bnv.y;
                }
            }
#pragma unroll
            for (int kc = 0; kc < 4; ++kc) {
#pragma unroll
                for (int nb = 0; nb < 4; ++nb) {
                    const int c = (ncb * 4 + nb) * 8 + g;       // cand in tile
                    const uint32_t sw = (uint32_t)((c & 7) << 4);
                    const uint32_t kb = (uint32_t)(kc * 32 + tig * 4);
                    uint32_t b0 = *reinterpret_cast<const uint32_t*>(
                        bsm + c * 128 + (kb ^ sw));
                    uint32_t b1 = *reinterpret_cast<const uint32_t*>(
                        bsm + c * 128 + ((kb + 16) ^ sw));
                    mma16816(acc[nb][0], afr[0][kc], b0, b1);
                    mma16816(acc[nb][1], afr[1][kc], b0, b1);
                }
            }
            // selection: acc IS the distance (bn - 2*dot), |x|^2 deferred
#pragma unroll
            for (int nb = 0; nb < 4; ++nb)
#pragma unroll
                for (int mb = 0; mb < 2; ++mb) {
                    float* h0 = h[mb * 2];       // row g + mb*16
                    float* h1 = h[mb * 2 + 1];   // row g + 8 + mb*16
                    if (acc[nb][mb][0] < h0[KSEL - 1]) bubble_insert(h0, acc[nb][mb][0]);
                    if (acc[nb][mb][1] < h0[KSEL - 1]) bubble_insert(h0, acc[nb][mb][1]);
                    if (acc[nb][mb][2] < h1[KSEL - 1]) bubble_insert(h1, acc[nb][mb][2]);
                    if (acc[nb][mb][3] < h1[KSEL - 1]) bubble_insert(h1, acc[nb][mb][3]);
                }
        }
        __syncthreads();                 // done reading slot before its restage
    }

    // ---- write the 4 per-row sorted lists ----
#pragma unroll
    for (int r = 0; r < 4; ++r) {
        int row = row_base + (r & 1) * 8 + (r >> 1) * 16 + g;
        float* pp = &g_partial[(((size_t)row * PARTS + part) * 4 + tig) * KSEL];
#pragma unroll
        for (int j = 0; j < KSEL; ++j) pp[j] = h[(r >> 1) * 2 + (r & 1)][j];
    }
}

// ---------------- final merge kernel ----------------
__global__ void final_kernel(const float* __restrict__ x, float* __restrict__ out) {
    int row = blockIdx.x * 256 + threadIdx.x;
    float best[KSEL];
#pragma unroll
    for (int j = 0; j < KSEL; ++j) best[j] = __int_as_float(0x7f800000);
    const float* p = &g_partial[(size_t)row * PARTS * 4 * KSEL];
    for (int l = 0; l < PARTS * 4; ++l) {
        const float* q = p + l * KSEL;
#pragma unroll
        for (int j = 0; j < KSEL; ++j) {
            float v = q[j];
            if (v < best[KSEL - 1]) bubble_insert(best, v);
            else break;                  // lists are sorted ascending
        }
    }
    float xn = 0.f;
    const float4* xr = reinterpret_cast<const float4*>(x) + (size_t)row * 16;
#pragma unroll
    for (int q = 0; q < 16; ++q) {
        float4 v = xr[q];
        xn = fmaf(v.x, v.x, xn); xn = fmaf(v.y, v.y, xn);
        xn = fmaf(v.z, v.z, xn); xn = fmaf(v.w, v.w, xn);
    }
    float s = 0.f;
#pragma unroll
    for (int j = 1; j < KSEL; ++j)       // drop self-match (best[0])
        s += sqrtf(fmaxf(xn + best[j], 0.f));
    out[row] = log1pf(s * (1.f / (KSEL - 1)));
}

// ---------------- launch ----------------
extern "C" void kernel_launch(void* const* d_in, const int* in_sizes, int n_in,
                              void* d_out, int out_size) {
    const float* a = (const float*)d_in[0];
    const float* b = (const float*)d_in[1];
    const float* x = a;
    const float* buf = b;
    if (in_sizes[0] > in_sizes[1]) { x = b; buf = a; }

    cudaFuncSetAttribute(pbe_mma_kernel,
                         cudaFuncAttributeMaxDynamicSharedMemorySize, SMEM_TOTAL);

    prep_buf_kernel<<<M_CANDS / 256, 256>>>(buf);
    prep_x_kernel<<<N_ROWS / 256, 256>>>(x);

    dim3 grid(PARTS, ROWTILES);
    pbe_mma_kernel<<<grid, THREADS, SMEM_TOTAL>>>();

    final_kernel<<<N_ROWS / 256, 256>>>(x, (float*)d_out);
}

// round 4
// speedup vs baseline: 5.3204x; 1.6051x over previous
#include <cuda_runtime.h>
#include <cuda_bf16.h>
#include <cstdint>

// ---------------- problem constants ----------------
#define M_CANDS 131072
#define N_ROWS  2048
#define DIM     64
#define KSEL    11                 // k+1 smallest; smallest (self) dropped later

// ---------------- tiling ----------------
#define PARTS    16                      // candidate partitions
#define ROWS_CTA 256                     // x rows per CTA (16 warps x 16 rows)
#define ROWTILES (N_ROWS / ROWS_CTA)     // 8
#define CPART    (M_CANDS / PARTS)       // 8192 candidates per CTA
#define TN       256                     // candidates per smem tile
#define NT       (CPART / TN)            // 32 tiles
#define THREADS  512
#define TILE_BYTES (TN * 128)            // 32768
#define BN_BYTES   (TN * 4)              // 1024

// ---------------- smem layout (bytes) ----------------
#define SM_MBAR  0                       // 3 mbarriers
#define SM_B     1024
#define SM_BN    (SM_B + 3 * TILE_BYTES)          // 99328
#define SMEM_TOTAL (SM_BN + 3 * BN_BYTES)         // 102400

#define POS_INF __int_as_float(0x7f800000)
#define NEG_INF __int_as_float(0xff800000)

// ---------------- device globals (allocation-free scratch) ----------------
__device__ __align__(128) __nv_bfloat16 g_bbf[(size_t)M_CANDS * DIM]; // -2*buf, bf16, tile-swizzled
__device__ __align__(16)  __nv_bfloat16 g_xbf[(size_t)N_ROWS * DIM];
__device__ __align__(16)  float g_bnorm[M_CANDS];
__device__ __align__(16)  float g_xnorm[N_ROWS];
__device__ __align__(16)  float g_partial[(size_t)N_ROWS * PARTS * KSEL];

// ---------------- helpers ----------------
__device__ __forceinline__ uint32_t smem_u32(const void* p) {
    return (uint32_t)__cvta_generic_to_shared(p);
}
#define SWZ128(off) ((off) ^ (((off) >> 3) & 0x70))

#define MBARRIER_INIT(mbar, cnt) \
    asm volatile("mbarrier.init.shared.b64 [%0], %1;" \
                 :: "r"((uint32_t)(mbar)), "r"((uint32_t)(cnt)) : "memory")
#define MBARRIER_EXPECT_TX(mbar, bytes) \
    asm volatile("mbarrier.arrive.expect_tx.shared.b64 _, [%0], %1;" \
                 :: "r"((uint32_t)(mbar)), "r"((uint32_t)(bytes)) : "memory")
#define MBARRIER_WAIT_PARITY(mbar, parity) do {                                   \
    uint32_t _m = (uint32_t)(mbar); uint32_t _p = (uint32_t)(parity);             \
    asm volatile("{\n\t.reg .pred P1;\n\t"                                        \
        "WAIT_LOOP_%=:\n\t"                                                       \
        "mbarrier.try_wait.parity.acquire.cta.shared::cta.b64 P1, [%0], %1, 0x989680;\n\t" \
        "@P1 bra.uni WAIT_DONE_%=;\n\t"                                           \
        "bra.uni WAIT_LOOP_%=;\n\t"                                               \
        "WAIT_DONE_%=:\n\t}" :: "r"(_m), "r"(_p) : "memory");                     \
} while (0)

__device__ __forceinline__ void bulk_g2s(uint32_t dst, const void* src,
                                         uint32_t bytes, uint32_t mbar) {
    asm volatile(
        "cp.async.bulk.shared::cluster.global.mbarrier::complete_tx::bytes "
        "[%0], [%1], %2, [%3];"
        :: "r"(dst), "l"(__cvta_generic_to_global(src)), "r"(bytes), "r"(mbar)
        : "memory");
}

// m16n8k16 row.col bf16 -> f32, D += A*B (D aliases C)
__device__ __forceinline__ void mma16816(float c[4], const uint32_t a[4],
                                         uint32_t b0, uint32_t b1) {
    asm volatile(
        "mma.sync.aligned.m16n8k16.row.col.f32.bf16.bf16.f32 "
        "{%0,%1,%2,%3}, {%4,%5,%6,%7}, {%8,%9}, {%0,%1,%2,%3};"
        : "+f"(c[0]), "+f"(c[1]), "+f"(c[2]), "+f"(c[3])
        : "r"(a[0]), "r"(a[1]), "r"(a[2]), "r"(a[3]), "r"(b0), "r"(b1));
}

// keep h[0..10] ascending; caller ensured v < h[10]
__device__ __forceinline__ void bubble_insert(float* h, float v) {
#pragma unroll
    for (int j = 0; j < KSEL; ++j) {
        float lo = fminf(h[j], v);
        v = fmaxf(h[j], v);
        h[j] = lo;
    }
}

// merge my ascending 11-list with lane^mask's; keep 11 smallest, ascending.
// min(a[i], b[10-i]) = multiset of the 11 smallest; result is bitonic ->
// static bitonic-merge cleanup on 16 elems (5 leading -inf pads).
__device__ __forceinline__ void merge11(float h[KSEL], int mask) {
    float b[KSEL];
#pragma unroll
    for (int j = 0; j < KSEL; ++j) b[j] = __shfl_xor_sync(0xffffffffu, h[j], mask);
    float c[16];
#pragma unroll
    for (int i = 0; i < 5; ++i) c[i] = NEG_INF;
#pragma unroll
    for (int i = 0; i < KSEL; ++i) c[5 + i] = fminf(h[i], b[10 - i]);
#pragma unroll
    for (int d = 8; d >= 1; d >>= 1)
#pragma unroll
        for (int i = 0; i < 16; ++i)
            if ((i & d) == 0) {
                float lo = fminf(c[i], c[i | d]);
                float hi = fmaxf(c[i], c[i | d]);
                c[i] = lo; c[i | d] = hi;
            }
#pragma unroll
    for (int i = 0; i < KSEL; ++i) h[i] = c[5 + i];
}

// ---------------- prep kernels ----------------
// writes -2*buf (bf16) into g_bbf, PRE-SWIZZLED per 32KB tile of 256 cands,
// so the main kernel can bulk-copy tiles verbatim into smem.
__global__ void prep_buf_kernel(const float* __restrict__ buf) {
    int c = blockIdx.x * 256 + threadIdx.x;
    const float4* s = reinterpret_cast<const float4*>(buf) + (size_t)c * 16;
    uint4 pk[8];
    uint32_t* pw = reinterpret_cast<uint32_t*>(pk);
    float n = 0.f;
#pragma unroll
    for (int q = 0; q < 16; ++q) {
        float4 v = s[q];
        n = fmaf(v.x, v.x, n); n = fmaf(v.y, v.y, n);
        n = fmaf(v.z, v.z, n); n = fmaf(v.w, v.w, n);
        __nv_bfloat162 a = __floats2bfloat162_rn(-2.f * v.x, -2.f * v.y);
        __nv_bfloat162 b = __floats2bfloat162_rn(-2.f * v.z, -2.f * v.w);
        pw[2 * q]     = reinterpret_cast<uint32_t&>(a);
        pw[2 * q + 1] = reinterpret_cast<uint32_t&>(b);
    }
    char* blk = reinterpret_cast<char*>(g_bbf) + (size_t)(c >> 8) * TILE_BYTES;
    uint32_t r = (uint32_t)(c & 255);
#pragma unroll
    for (int q = 0; q < 8; ++q)
        *reinterpret_cast<uint4*>(blk + SWZ128(r * 128 + q * 16)) = pk[q];
    g_bnorm[c] = n;
}

__global__ void prep_x_kernel(const float* __restrict__ x) {
    int c = blockIdx.x * 256 + threadIdx.x;
    const float4* s = reinterpret_cast<const float4*>(x) + (size_t)c * 16;
    uint4 pk[8];
    uint32_t* pw = reinterpret_cast<uint32_t*>(pk);
    float n = 0.f;
#pragma unroll
    for (int q = 0; q < 16; ++q) {
        float4 v = s[q];
        n = fmaf(v.x, v.x, n); n = fmaf(v.y, v.y, n);
        n = fmaf(v.z, v.z, n); n = fmaf(v.w, v.w, n);
        __nv_bfloat162 a = __floats2bfloat162_rn(v.x, v.y);
        __nv_bfloat162 b = __floats2bfloat162_rn(v.z, v.w);
        pw[2 * q]     = reinterpret_cast<uint32_t&>(a);
        pw[2 * q + 1] = reinterpret_cast<uint32_t&>(b);
    }
    uint4* dst = reinterpret_cast<uint4*>(g_xbf) + (size_t)c * 8;
#pragma unroll
    for (int i = 0; i < 8; ++i) dst[i] = pk[i];
    g_xnorm[c] = n;
}

// ---------------- main fused GEMM + top-k kernel ----------------
extern __shared__ char smem[];

__global__ void __launch_bounds__(THREADS, 1)
pbe_mma_kernel() {
    const int tid  = threadIdx.x;
    const int lane = tid & 31;
    const int w    = tid >> 5;           // 0..15
    const int g    = lane >> 2;          // 0..7
    const int tig  = lane & 3;           // 0..3
    const int part = blockIdx.x;
    const int rt   = blockIdx.y;
    const int cand_base = part * CPART;
    const int row_base  = rt * ROWS_CTA + w * 16;

    const uint32_t sbase = smem_u32(smem);
    const uint32_t mb0   = sbase + SM_MBAR;

    // ---- A fragments: 1 m-block (16 rows) per warp, persistent ----
    uint32_t afr[4][4];
    {
        const uint32_t* x0 = reinterpret_cast<const uint32_t*>(
            g_xbf + (size_t)(row_base + g) * DIM);
        const uint32_t* x1 = reinterpret_cast<const uint32_t*>(
            g_xbf + (size_t)(row_base + g + 8) * DIM);
#pragma unroll
        for (int kc = 0; kc < 4; ++kc) {
            afr[kc][0] = x0[kc * 8 + tig];
            afr[kc][1] = x1[kc * 8 + tig];
            afr[kc][2] = x0[kc * 8 + tig + 4];
            afr[kc][3] = x1[kc * 8 + tig + 4];
        }
    }

    // ---- mbarriers + prologue staging ----
    if (tid == 0) {
        MBARRIER_INIT(mb0 + 0,  1);
        MBARRIER_INIT(mb0 + 8,  1);
        MBARRIER_INIT(mb0 + 16, 1);
    }
    __syncthreads();

    auto issue = [&](int t) {            // thread 0 only
        int s = t % 3;
        uint32_t bar = mb0 + s * 8;
        MBARRIER_EXPECT_TX(bar, TILE_BYTES + BN_BYTES);
        bulk_g2s(sbase + SM_B + s * TILE_BYTES,
                 reinterpret_cast<const char*>(g_bbf)
                   + (size_t)(cand_base + t * TN) * 128,
                 TILE_BYTES, bar);
        bulk_g2s(sbase + SM_BN + s * BN_BYTES,
                 g_bnorm + cand_base + t * TN, BN_BYTES, bar);
    };
    if (tid == 0) { issue(0); issue(1); }

    // ---- top-11 lists for this thread's 2 rows ----
    float h[2][KSEL];
#pragma unroll
    for (int r = 0; r < 2; ++r)
#pragma unroll
        for (int j = 0; j < KSEL; ++j) h[r][j] = POS_INF;

    uint32_t ph[3] = {0, 0, 0};

    for (int t = 0; t < NT; ++t) {
        const int slot = t % 3;
        MBARRIER_WAIT_PARITY(mb0 + slot * 8, ph[slot]);
        ph[slot] ^= 1;
        __syncthreads();                 // everyone done with slot (t-1)%3

        if (t + 2 < NT && tid == 0) issue(t + 2);

        const char*  bsm = smem + SM_B + slot * TILE_BYTES;
        const float* bns = reinterpret_cast<const float*>(smem + SM_BN + slot * BN_BYTES);

#pragma unroll
        for (int ncb = 0; ncb < 8; ++ncb) {              // 8 chunks x 32 cands
            float acc[4][4];
#pragma unroll
            for (int nb = 0; nb < 4; ++nb) {
                const float2 bnv = *reinterpret_cast<const float2*>(
                    &bns[(ncb * 4 + nb) * 8 + tig * 2]);
                acc[nb][0] = bnv.x; acc[nb][1] = bnv.y;
                acc[nb][2] = bnv.x; acc[nb][3] = bnv.y;
            }
#pragma unroll
            for (int kc = 0; kc < 4; ++kc) {
#pragma unroll
                for (int nb = 0; nb < 4; ++nb) {
                    const int c = (ncb * 4 + nb) * 8 + g;
                    const uint32_t sw = (uint32_t)((c & 7) << 4);
                    const uint32_t kb = (uint32_t)(kc * 32 + tig * 4);
                    uint32_t b0 = *reinterpret_cast<const uint32_t*>(
                        bsm + c * 128 + (kb ^ sw));
                    uint32_t b1 = *reinterpret_cast<const uint32_t*>(
                        bsm + c * 128 + ((kb + 16) ^ sw));
                    mma16816(acc[nb], afr[kc], b0, b1);
                }
            }
            // acc IS the distance (bn - 2*dot); |x|^2 deferred to the end
#pragma unroll
            for (int nb = 0; nb < 4; ++nb) {
                if (acc[nb][0] < h[0][KSEL - 1]) bubble_insert(h[0], acc[nb][0]);
                if (acc[nb][1] < h[0][KSEL - 1]) bubble_insert(h[0], acc[nb][1]);
                if (acc[nb][2] < h[1][KSEL - 1]) bubble_insert(h[1], acc[nb][2]);
                if (acc[nb][3] < h[1][KSEL - 1]) bubble_insert(h[1], acc[nb][3]);
            }
        }
        __syncthreads();                 // done reading slot before re-fill
    }

    // ---- merge across the 4 tig lanes; tig 0 writes 1 list per row/part ----
    merge11(h[0], 1); merge11(h[0], 2);
    merge11(h[1], 1); merge11(h[1], 2);
    if (tig == 0) {
        float* p0 = &g_partial[((size_t)(row_base + g)     * PARTS + part) * KSEL];
        float* p1 = &g_partial[((size_t)(row_base + g + 8) * PARTS + part) * KSEL];
#pragma unroll
        for (int j = 0; j < KSEL; ++j) { p0[j] = h[0][j]; p1[j] = h[1][j]; }
    }
}

// ---------------- final merge kernel: one warp per row ----------------
__global__ void final_kernel(float* __restrict__ out) {
    const int row  = blockIdx.x * 8 + (threadIdx.x >> 5);
    const int lane = threadIdx.x & 31;
    float h[KSEL];
    if (lane < PARTS) {
        const float* p = &g_partial[((size_t)row * PARTS + lane) * KSEL];
#pragma unroll
        for (int j = 0; j < KSEL; ++j) h[j] = p[j];
    } else {
#pragma unroll
        for (int j = 0; j < KSEL; ++j) h[j] = POS_INF;
    }
    merge11(h, 1); merge11(h, 2); merge11(h, 4); merge11(h, 8);
    if (lane == 0) {
        float xn = g_xnorm[row];
        float s = 0.f;
#pragma unroll
        for (int j = 1; j < KSEL; ++j)          // drop self-match (h[0])
            s += sqrtf(fmaxf(xn + h[j], 0.f));
        out[row] = log1pf(s * (1.f / (KSEL - 1)));
    }
}

// ---------------- launch ----------------
extern "C" void kernel_launch(void* const* d_in, const int* in_sizes, int n_in,
                              void* d_out, int out_size) {
    const float* a = (const float*)d_in[0];
    const float* b = (const float*)d_in[1];
    const float* x = a;
    const float* buf = b;
    if (in_sizes[0] > in_sizes[1]) { x = b; buf = a; }

    cudaFuncSetAttribute(pbe_mma_kernel,
                         cudaFuncAttributeMaxDynamicSharedMemorySize, SMEM_TOTAL);

    prep_buf_kernel<<<M_CANDS / 256, 256>>>(buf);
    prep_x_kernel<<<N_ROWS / 256, 256>>>(x);

    dim3 grid(PARTS, ROWTILES);
    pbe_mma_kernel<<<grid, THREADS, SMEM_TOTAL>>>();

    final_kernel<<<N_ROWS / 8, 256>>>((float*)d_out);
}